// round 1
// baseline (speedup 1.0000x reference)
#include <cuda_runtime.h>

#define B_ 32
#define L_ 1024
#define D_ 64

// scratch: energyT[b][e][j]  (e is the GEMM-K dim of the scores GEMM)
__device__ float g_energyT[B_ * D_ * L_];

// packed fp32x2 FMA: d = a*b + d   (sm_103a FFMA2 — only reachable via PTX)
__device__ __forceinline__ void ffma2(float2& d, const float2 a, const float2 b) {
    asm("fma.rn.f32x2 %0, %1, %2, %0;"
        : "+l"(reinterpret_cast<unsigned long long&>(d))
        : "l"(reinterpret_cast<const unsigned long long&>(a)),
          "l"(reinterpret_cast<const unsigned long long&>(b)));
}

// ---------------------------------------------------------------------------
// Kernel 1: energyT[b][e][j] = sum_d enc[b][j][d] * W[e][d] + bias[e]
// grid (8 j-blocks, 32 b), 256 threads
// ---------------------------------------------------------------------------
__global__ __launch_bounds__(256) void energy_kernel(
    const float* __restrict__ enc, const float* __restrict__ W,
    const float* __restrict__ bias) {
    __shared__ float Wt[D_][D_];     // [d][e]  (transposed W)
    __shared__ float encs[D_][128];  // [d][j_local] (transposed enc tile)
    const int b = blockIdx.y, jb = blockIdx.x;
    const int tid = threadIdx.x;

    // load W (64x64) transposed into smem
    const float4* W4 = reinterpret_cast<const float4*>(W);
#pragma unroll
    for (int i = 0; i < 4; i++) {
        int f = tid + i * 256;           // 1024 float4s
        int e = f >> 4, dq = f & 15;
        float4 w = W4[f];
        Wt[dq * 4 + 0][e] = w.x; Wt[dq * 4 + 1][e] = w.y;
        Wt[dq * 4 + 2][e] = w.z; Wt[dq * 4 + 3][e] = w.w;
    }
    // load enc tile (128 j rows x 64 d) transposed
    const float4* enc4 =
        reinterpret_cast<const float4*>(enc + ((size_t)b * L_ + (size_t)jb * 128) * D_);
#pragma unroll
    for (int i = 0; i < 8; i++) {
        int f = tid + i * 256;           // 2048 float4s
        int j = f >> 4, dq = f & 15;
        float4 v = enc4[f];
        encs[dq * 4 + 0][j] = v.x; encs[dq * 4 + 1][j] = v.y;
        encs[dq * 4 + 2][j] = v.z; encs[dq * 4 + 3][j] = v.w;
    }
    __syncthreads();

    const int w = tid >> 5, lane = tid & 31;
    const int e0 = w * 8;                // warp owns 8 e-rows
    float2 acc[8][2];
#pragma unroll
    for (int e = 0; e < 8; e++) {
        acc[e][0] = make_float2(0.f, 0.f);
        acc[e][1] = make_float2(0.f, 0.f);
    }
#pragma unroll 4
    for (int d = 0; d < D_; d++) {
        float4 ev = *reinterpret_cast<const float4*>(&encs[d][lane * 4]);
        float2 ev01 = make_float2(ev.x, ev.y);
        float2 ev23 = make_float2(ev.z, ev.w);
        float4 wa = *reinterpret_cast<const float4*>(&Wt[d][e0]);
        float4 wb = *reinterpret_cast<const float4*>(&Wt[d][e0 + 4]);
        float wv[8] = {wa.x, wa.y, wa.z, wa.w, wb.x, wb.y, wb.z, wb.w};
#pragma unroll
        for (int e = 0; e < 8; e++) {
            float2 ee = make_float2(wv[e], wv[e]);
            ffma2(acc[e][0], ee, ev01);
            ffma2(acc[e][1], ee, ev23);
        }
    }
#pragma unroll
    for (int e = 0; e < 8; e++) {
        float bb = bias[e0 + e];
        float4 o = make_float4(acc[e][0].x + bb, acc[e][0].y + bb,
                               acc[e][1].x + bb, acc[e][1].y + bb);
        *reinterpret_cast<float4*>(
            &g_energyT[(((size_t)b * D_ + e0 + e) << 10) + jb * 128 + lane * 4]) = o;
    }
}

// ---------------------------------------------------------------------------
// Kernel 2: scores[t,b,j] = sum_k energyT[b][k][j] * enc[b][t][k]
//           then zero diag, softmax over j, write out[t][b][j].
// grid (32 t-blocks, 32 b), 256 threads. CTA tile: 32 t x 1024 j.
// thread: warp = (tg, jh); owns 8 t-rows, 16 j-cols (strided lane*4 + m*128).
// ---------------------------------------------------------------------------
__global__ __launch_bounds__(256, 1) void scores_kernel(
    const float* __restrict__ enc, float* __restrict__ out) {
    __shared__ float enc_s[D_][36];   // [k][t], padded stride
    __shared__ float redmax[2][32];
    __shared__ float redsum[2][32];
    const int b = blockIdx.y, tb = blockIdx.x;
    const int tid = threadIdx.x, warp = tid >> 5, lane = tid & 31;
    const int tg = warp >> 1, jh = warp & 1;

    // load enc tile (32 t x 64 k) transposed into smem
    const float4* enc4 =
        reinterpret_cast<const float4*>(enc + ((size_t)b * L_ + (size_t)tb * 32) * D_);
#pragma unroll
    for (int i = 0; i < 2; i++) {
        int f = tid + i * 256;          // 512 float4s
        int t = f >> 4, dq = f & 15;
        float4 v = enc4[f];
        enc_s[dq * 4 + 0][t] = v.x; enc_s[dq * 4 + 1][t] = v.y;
        enc_s[dq * 4 + 2][t] = v.z; enc_s[dq * 4 + 3][t] = v.w;
    }
    __syncthreads();

    float2 acc[8][8];
#pragma unroll
    for (int tt = 0; tt < 8; tt++)
#pragma unroll
        for (int c = 0; c < 8; c++) acc[tt][c] = make_float2(0.f, 0.f);

    const float* ebase = g_energyT + (size_t)b * D_ * L_ + jh * 512 + lane * 4;

    float4 g[4];
#pragma unroll
    for (int m = 0; m < 4; m++)
        g[m] = *reinterpret_cast<const float4*>(ebase + m * 128);

#pragma unroll 1
    for (int k = 0; k < D_; k++) {
        float4 gn[4];
        if (k < D_ - 1) {
            const float* p = ebase + (size_t)(k + 1) * L_;
#pragma unroll
            for (int m = 0; m < 4; m++)
                gn[m] = *reinterpret_cast<const float4*>(p + m * 128);
        }
        float4 ea = *reinterpret_cast<const float4*>(&enc_s[k][tg * 8]);
        float4 eb = *reinterpret_cast<const float4*>(&enc_s[k][tg * 8 + 4]);
        float ev[8] = {ea.x, ea.y, ea.z, ea.w, eb.x, eb.y, eb.z, eb.w};
#pragma unroll
        for (int tt = 0; tt < 8; tt++) {
            float2 ee = make_float2(ev[tt], ev[tt]);
#pragma unroll
            for (int m = 0; m < 4; m++) {
                ffma2(acc[tt][2 * m],     ee, make_float2(g[m].x, g[m].y));
                ffma2(acc[tt][2 * m + 1], ee, make_float2(g[m].z, g[m].w));
            }
        }
        if (k < D_ - 1) {
#pragma unroll
            for (int m = 0; m < 4; m++) g[m] = gn[m];
        }
    }

    const int t0 = tb * 32 + tg * 8;

    // zero diagonal: scores[t, b, t] = 0
#pragma unroll
    for (int tt = 0; tt < 8; tt++) {
        const int t = t0 + tt;
#pragma unroll
        for (int m = 0; m < 4; m++) {
            const int j4 = jh * 512 + m * 128 + lane * 4;
            if (j4 + 0 == t) acc[tt][2 * m].x     = 0.f;
            if (j4 + 1 == t) acc[tt][2 * m].y     = 0.f;
            if (j4 + 2 == t) acc[tt][2 * m + 1].x = 0.f;
            if (j4 + 3 == t) acc[tt][2 * m + 1].y = 0.f;
        }
    }

    // row max (per t-row over 1024 j spread across 2 warps)
    float mx[8];
#pragma unroll
    for (int tt = 0; tt < 8; tt++) {
        float m = -3.4e38f;
#pragma unroll
        for (int c = 0; c < 8; c++)
            m = fmaxf(m, fmaxf(acc[tt][c].x, acc[tt][c].y));
#pragma unroll
        for (int o = 16; o > 0; o >>= 1)
            m = fmaxf(m, __shfl_xor_sync(0xffffffffu, m, o));
        mx[tt] = m;
    }
    if (lane == 0) {
#pragma unroll
        for (int tt = 0; tt < 8; tt++) redmax[jh][tg * 8 + tt] = mx[tt];
    }
    __syncthreads();

    // exp + row sum
    float sm[8];
#pragma unroll
    for (int tt = 0; tt < 8; tt++) {
        const float rm = fmaxf(redmax[0][tg * 8 + tt], redmax[1][tg * 8 + tt]);
        float s = 0.f;
#pragma unroll
        for (int c = 0; c < 8; c++) {
            acc[tt][c].x = __expf(acc[tt][c].x - rm);
            acc[tt][c].y = __expf(acc[tt][c].y - rm);
            s += acc[tt][c].x + acc[tt][c].y;
        }
#pragma unroll
        for (int o = 16; o > 0; o >>= 1)
            s += __shfl_xor_sync(0xffffffffu, s, o);
        sm[tt] = s;
    }
    if (lane == 0) {
#pragma unroll
        for (int tt = 0; tt < 8; tt++) redsum[jh][tg * 8 + tt] = sm[tt];
    }
    __syncthreads();

    // normalize + store: out[t][b][j]
#pragma unroll
    for (int tt = 0; tt < 8; tt++) {
        const float rinv = 1.0f / (redsum[0][tg * 8 + tt] + redsum[1][tg * 8 + tt]);
        float4* optr = reinterpret_cast<float4*>(
            out + ((size_t)(t0 + tt) * B_ + b) * L_ + jh * 512 + lane * 4);
#pragma unroll
        for (int m = 0; m < 4; m++) {
            float4 o = make_float4(acc[tt][2 * m].x * rinv, acc[tt][2 * m].y * rinv,
                                   acc[tt][2 * m + 1].x * rinv, acc[tt][2 * m + 1].y * rinv);
            optr[m * 32] = o;
        }
    }
}

extern "C" void kernel_launch(void* const* d_in, const int* in_sizes, int n_in,
                              void* d_out, int out_size) {
    (void)in_sizes; (void)n_in; (void)out_size;
    const float* enc  = (const float*)d_in[0];
    const float* W    = (const float*)d_in[1];
    const float* bias = (const float*)d_in[2];
    // d_in[3] = target_length (== 1024 == L, baked into the kernel)
    float* out = (float*)d_out;

    energy_kernel<<<dim3(8, 32), 256>>>(enc, W, bias);
    scores_kernel<<<dim3(32, 32), 256>>>(enc, out);
}

// round 2
// speedup vs baseline: 1.6690x; 1.6690x over previous
#include <cuda_runtime.h>

#define B_ 32
#define L_ 1024
#define D_ 64
#define SLAB_K 8          // k-rows per smem slab
#define NSLAB (D_ / SLAB_K)

// scratch: energyT[b][e][j]  (e is the GEMM-K dim of the scores GEMM)
__device__ float g_energyT[B_ * D_ * L_];

// packed fp32x2 FMA: d = a*b + d   (sm_103a FFMA2 — only reachable via PTX)
__device__ __forceinline__ void ffma2(float2& d, const float2 a, const float2 b) {
    asm("fma.rn.f32x2 %0, %1, %2, %0;"
        : "+l"(reinterpret_cast<unsigned long long&>(d))
        : "l"(reinterpret_cast<const unsigned long long&>(a)),
          "l"(reinterpret_cast<const unsigned long long&>(b)));
}

__device__ __forceinline__ void cp16(float* dst_smem, const float* src) {
    unsigned s = (unsigned)__cvta_generic_to_shared(dst_smem);
    asm volatile("cp.async.cg.shared.global [%0], [%1], 16;\n" :: "r"(s), "l"(src));
}
__device__ __forceinline__ void cp_commit() {
    asm volatile("cp.async.commit_group;\n");
}
template <int N>
__device__ __forceinline__ void cp_wait() {
    asm volatile("cp.async.wait_group %0;\n" :: "n"(N));
}

// ---------------------------------------------------------------------------
// Kernel 1: energyT[b][e][j] = sum_d enc[b][j][d] * W[e][d] + bias[e]
// grid (8 j-blocks, 32 b), 256 threads
// ---------------------------------------------------------------------------
__global__ __launch_bounds__(256) void energy_kernel(
    const float* __restrict__ enc, const float* __restrict__ W,
    const float* __restrict__ bias) {
    __shared__ float Wt[D_][D_];     // [d][e]  (transposed W)
    __shared__ float encs[D_][128];  // [d][j_local] (transposed enc tile)
    const int b = blockIdx.y, jb = blockIdx.x;
    const int tid = threadIdx.x;

    const float4* W4 = reinterpret_cast<const float4*>(W);
#pragma unroll
    for (int i = 0; i < 4; i++) {
        int f = tid + i * 256;           // 1024 float4s
        int e = f >> 4, dq = f & 15;
        float4 w = W4[f];
        Wt[dq * 4 + 0][e] = w.x; Wt[dq * 4 + 1][e] = w.y;
        Wt[dq * 4 + 2][e] = w.z; Wt[dq * 4 + 3][e] = w.w;
    }
    const float4* enc4 =
        reinterpret_cast<const float4*>(enc + ((size_t)b * L_ + (size_t)jb * 128) * D_);
#pragma unroll
    for (int i = 0; i < 8; i++) {
        int f = tid + i * 256;           // 2048 float4s
        int j = f >> 4, dq = f & 15;
        float4 v = enc4[f];
        encs[dq * 4 + 0][j] = v.x; encs[dq * 4 + 1][j] = v.y;
        encs[dq * 4 + 2][j] = v.z; encs[dq * 4 + 3][j] = v.w;
    }
    __syncthreads();

    const int w = tid >> 5, lane = tid & 31;
    const int e0 = w * 8;                // warp owns 8 e-rows
    float2 acc[8][2];
#pragma unroll
    for (int e = 0; e < 8; e++) {
        acc[e][0] = make_float2(0.f, 0.f);
        acc[e][1] = make_float2(0.f, 0.f);
    }
#pragma unroll 4
    for (int d = 0; d < D_; d++) {
        float4 ev = *reinterpret_cast<const float4*>(&encs[d][lane * 4]);
        float2 ev01 = make_float2(ev.x, ev.y);
        float2 ev23 = make_float2(ev.z, ev.w);
        float4 wa = *reinterpret_cast<const float4*>(&Wt[d][e0]);
        float4 wb = *reinterpret_cast<const float4*>(&Wt[d][e0 + 4]);
        float wv[8] = {wa.x, wa.y, wa.z, wa.w, wb.x, wb.y, wb.z, wb.w};
#pragma unroll
        for (int e = 0; e < 8; e++) {
            float2 ee = make_float2(wv[e], wv[e]);
            ffma2(acc[e][0], ee, ev01);
            ffma2(acc[e][1], ee, ev23);
        }
    }
#pragma unroll
    for (int e = 0; e < 8; e++) {
        float bb = bias[e0 + e];
        float4 o = make_float4(acc[e][0].x + bb, acc[e][0].y + bb,
                               acc[e][1].x + bb, acc[e][1].y + bb);
        *reinterpret_cast<float4*>(
            &g_energyT[(((size_t)b * D_ + e0 + e) << 10) + jb * 128 + lane * 4]) = o;
    }
}

// ---------------------------------------------------------------------------
// Kernel 2: scores[t,b,j] = sum_k energyT[b][k][j] * enc[b][t][k]
//           cp.async double-buffered k-slabs of energyT in smem,
//           then zero diag, softmax over j, write out[t][b][j].
// grid (32 t-blocks, 32 b), 256 threads. CTA tile: 32 t x 1024 j.
// ---------------------------------------------------------------------------
__global__ __launch_bounds__(256, 1) void scores_kernel(
    const float* __restrict__ enc, float* __restrict__ out) {
    extern __shared__ float smem[];
    float* es   = smem;                         // [2][SLAB_K][1024]
    float* encs = smem + 2 * SLAB_K * 1024;     // [64][36] (k-major, padded)
    float* redm = encs + D_ * 36;               // [2][32]
    float* reds = redm + 64;                    // [2][32]

    const int b = blockIdx.y, tb = blockIdx.x;
    const int tid = threadIdx.x, warp = tid >> 5, lane = tid & 31;
    const int tg = warp >> 1, jh = warp & 1;

    // load enc tile (32 t x 64 k) transposed into smem [k][t]
    const float4* enc4 =
        reinterpret_cast<const float4*>(enc + ((size_t)b * L_ + (size_t)tb * 32) * D_);
#pragma unroll
    for (int i = 0; i < 2; i++) {
        int f = tid + i * 256;          // 512 float4s
        int t = f >> 4, dq = f & 15;
        float4 v = enc4[f];
        encs[(dq * 4 + 0) * 36 + t] = v.x; encs[(dq * 4 + 1) * 36 + t] = v.y;
        encs[(dq * 4 + 2) * 36 + t] = v.z; encs[(dq * 4 + 3) * 36 + t] = v.w;
    }

    const float* ebase = g_energyT + (size_t)b * D_ * L_;

    // prefetch slab 0 and 1 (each: SLAB_K*1024 floats = 2048 float4, 8/thread)
#pragma unroll
    for (int i = 0; i < 8; i++)
        cp16(es + (tid + i * 256) * 4, ebase + (tid + i * 256) * 4);
    cp_commit();
#pragma unroll
    for (int i = 0; i < 8; i++)
        cp16(es + SLAB_K * 1024 + (tid + i * 256) * 4,
             ebase + SLAB_K * 1024 + (tid + i * 256) * 4);
    cp_commit();

    float2 acc[8][8];
#pragma unroll
    for (int tt = 0; tt < 8; tt++)
#pragma unroll
        for (int c = 0; c < 8; c++) acc[tt][c] = make_float2(0.f, 0.f);

#pragma unroll 1
    for (int s = 0; s < NSLAB; s++) {
        cp_wait<1>();          // slab s resident
        __syncthreads();

        const float* eb0 = es + (s & 1) * (SLAB_K * 1024) + jh * 512 + lane * 4;
#pragma unroll
        for (int kk = 0; kk < SLAB_K; kk++) {
            const int k = s * SLAB_K + kk;
            const float* er = eb0 + kk * 1024;
            float4 g0 = *reinterpret_cast<const float4*>(er);
            float4 g1 = *reinterpret_cast<const float4*>(er + 128);
            float4 g2 = *reinterpret_cast<const float4*>(er + 256);
            float4 g3 = *reinterpret_cast<const float4*>(er + 384);
            float4 ea = *reinterpret_cast<const float4*>(&encs[k * 36 + tg * 8]);
            float4 eb = *reinterpret_cast<const float4*>(&encs[k * 36 + tg * 8 + 4]);
            float ev[8] = {ea.x, ea.y, ea.z, ea.w, eb.x, eb.y, eb.z, eb.w};
            float2 gl[8] = {make_float2(g0.x, g0.y), make_float2(g0.z, g0.w),
                            make_float2(g1.x, g1.y), make_float2(g1.z, g1.w),
                            make_float2(g2.x, g2.y), make_float2(g2.z, g2.w),
                            make_float2(g3.x, g3.y), make_float2(g3.z, g3.w)};
#pragma unroll
            for (int tt = 0; tt < 8; tt++) {
                float2 ee = make_float2(ev[tt], ev[tt]);
#pragma unroll
                for (int c = 0; c < 8; c++) ffma2(acc[tt][c], ee, gl[c]);
            }
        }
        __syncthreads();       // all warps done reading buffer (s&1)

        if (s + 2 < NSLAB) {   // refill the buffer we just finished
            const float* src = ebase + (size_t)(s + 2) * SLAB_K * 1024;
            float* dst = es + (s & 1) * (SLAB_K * 1024);
#pragma unroll
            for (int i = 0; i < 8; i++)
                cp16(dst + (tid + i * 256) * 4, src + (tid + i * 256) * 4);
        }
        cp_commit();           // keep group count advancing every iter
    }

    const int t0 = tb * 32 + tg * 8;

    // zero diagonal: scores[t, b, t] = 0
#pragma unroll
    for (int tt = 0; tt < 8; tt++) {
        const int t = t0 + tt;
#pragma unroll
        for (int m = 0; m < 4; m++) {
            const int j4 = jh * 512 + m * 128 + lane * 4;
            if (j4 + 0 == t) acc[tt][2 * m].x     = 0.f;
            if (j4 + 1 == t) acc[tt][2 * m].y     = 0.f;
            if (j4 + 2 == t) acc[tt][2 * m + 1].x = 0.f;
            if (j4 + 3 == t) acc[tt][2 * m + 1].y = 0.f;
        }
    }

    // row max (per t-row over 1024 j spread across 2 warps)
    float mx[8];
#pragma unroll
    for (int tt = 0; tt < 8; tt++) {
        float m = -3.4e38f;
#pragma unroll
        for (int c = 0; c < 8; c++)
            m = fmaxf(m, fmaxf(acc[tt][c].x, acc[tt][c].y));
#pragma unroll
        for (int o = 16; o > 0; o >>= 1)
            m = fmaxf(m, __shfl_xor_sync(0xffffffffu, m, o));
        mx[tt] = m;
    }
    if (lane == 0) {
#pragma unroll
        for (int tt = 0; tt < 8; tt++) redm[jh * 32 + tg * 8 + tt] = mx[tt];
    }
    __syncthreads();

    // exp + row sum
    float sm[8];
#pragma unroll
    for (int tt = 0; tt < 8; tt++) {
        const float rm = fmaxf(redm[tg * 8 + tt], redm[32 + tg * 8 + tt]);
        float s = 0.f;
#pragma unroll
        for (int c = 0; c < 8; c++) {
            acc[tt][c].x = __expf(acc[tt][c].x - rm);
            acc[tt][c].y = __expf(acc[tt][c].y - rm);
            s += acc[tt][c].x + acc[tt][c].y;
        }
#pragma unroll
        for (int o = 16; o > 0; o >>= 1)
            s += __shfl_xor_sync(0xffffffffu, s, o);
        sm[tt] = s;
    }
    if (lane == 0) {
#pragma unroll
        for (int tt = 0; tt < 8; tt++) reds[jh * 32 + tg * 8 + tt] = sm[tt];
    }
    __syncthreads();

    // normalize + store: out[t][b][j]
#pragma unroll
    for (int tt = 0; tt < 8; tt++) {
        const float rinv = 1.0f / (reds[tg * 8 + tt] + reds[32 + tg * 8 + tt]);
        float4* optr = reinterpret_cast<float4*>(
            out + ((size_t)(t0 + tt) * B_ + b) * L_ + jh * 512 + lane * 4);
#pragma unroll
        for (int m = 0; m < 4; m++) {
            float4 o = make_float4(acc[tt][2 * m].x * rinv, acc[tt][2 * m].y * rinv,
                                   acc[tt][2 * m + 1].x * rinv, acc[tt][2 * m + 1].y * rinv);
            optr[m * 32] = o;
        }
    }
}

extern "C" void kernel_launch(void* const* d_in, const int* in_sizes, int n_in,
                              void* d_out, int out_size) {
    (void)in_sizes; (void)n_in; (void)out_size;
    const float* enc  = (const float*)d_in[0];
    const float* W    = (const float*)d_in[1];
    const float* bias = (const float*)d_in[2];
    float* out = (float*)d_out;

    // dynamic smem: 2*8*1024 (slabs) + 64*36 (enc) + 128 (reductions) floats
    const int smem_bytes = (2 * SLAB_K * 1024 + D_ * 36 + 128) * sizeof(float);
    static int configured = 0;
    if (!configured) {
        cudaFuncSetAttribute(scores_kernel,
                             cudaFuncAttributeMaxDynamicSharedMemorySize, smem_bytes);
        configured = 1;
    }

    energy_kernel<<<dim3(8, 32), 256>>>(enc, W, bias);
    scores_kernel<<<dim3(32, 32), 256, smem_bytes>>>(enc, out);
}